// round 12
// baseline (speedup 1.0000x reference)
#include <cuda_runtime.h>
#include <cstdint>

#define HID   32
#define NCOL  224
#define TPB   224     // one thread per gate column; warp w == gate w
#define SPB   4       // samples (independent chains) per block
#define NSTEP 2047
#define NB    512
#define SEQ   2048
#define NTY   20
#define BETA  0.1f

typedef unsigned long long ull;

__device__ __forceinline__ unsigned su32(const void* p) {
    return (unsigned)__cvta_generic_to_shared(p);
}
__device__ __forceinline__ void ffma2(ull& d, ull a, ull b) {
    asm("fma.rn.f32x2 %0, %1, %2, %0;" : "+l"(d) : "l"(a), "l"(b));
}
__device__ __forceinline__ ull fadd2(ull a, ull b) {
    ull d; asm("add.rn.f32x2 %0, %1, %2;" : "=l"(d) : "l"(a), "l"(b)); return d;
}
__device__ __forceinline__ ull pack2(float a, float b) {
    ull d; asm("mov.b64 %0, {%1, %2};" : "=l"(d) : "f"(a), "f"(b)); return d;
}
__device__ __forceinline__ float sum2(ull v) {
    float a, b; asm("mov.b64 {%0, %1}, %2;" : "=f"(a), "=f"(b) : "l"(v));
    return a + b;
}
__device__ __forceinline__ void lds128(ull& a, ull& b, unsigned addr) {
    asm volatile("ld.shared.v2.u64 {%0, %1}, [%2];" : "=l"(a), "=l"(b) : "r"(addr));
}

__device__ __forceinline__ float tanh_fast(float x) {
    float e = __expf(-2.f * fabsf(x));          // overflow-safe: e in (0,1]
    float t = __fdividef(1.f - e, 1.f + e);
    return copysignf(t, x);
}
__device__ __forceinline__ float sigmoid_fast(float x) {
    return __fdividef(1.f, 1.f + __expf(-x));
}

__global__ __launch_bounds__(TPB, 2)
void hawkes_kernel(const int* __restrict__ types,
                   const float* __restrict__ dtime,
                   const float* __restrict__ emb,
                   const float* __restrict__ W,
                   const float* __restrict__ bvec,
                   float* __restrict__ out)
{
    __shared__ float s_gx[NTY * NCOL];               // x-side pre-activation (incl. bias)
    __shared__ float s_act[SPB][NCOL];               // per-sample activations (slot6 = edt)
    __shared__ __align__(16) float s_h[SPB][HID];    // per-sample hidden state
    __shared__ float s_emb[NTY * HID];
    __shared__ unsigned char s_ty[SPB][NSTEP + 1];
    __shared__ float s_dt[SPB][NSTEP];

    const int tid  = threadIdx.x;
    const int warp = tid >> 5;          // 0..6 == gate index (warp-uniform)
    const int lane = tid & 31;
    const int blk  = blockIdx.x;

    // ---- prologue: stage 4 samples' streams + embedding ----
    for (int i = tid; i < NTY * HID; i += TPB) s_emb[i] = emb[i];
    for (int i = tid; i < SPB * NSTEP; i += TPB) {
        const int ss = i / NSTEP, t = i - ss * NSTEP;
        s_ty[ss][t] = (unsigned char)types[(blk * SPB + ss) * SEQ + t];
        s_dt[ss][t] = dtime[(blk * SPB + ss) * SEQ + t + 1];
    }
    if (tid < SPB * HID) s_h[tid >> 5][tid & 31] = 0.f;
    __syncthreads();

    // ---- gx lookup table (one column per thread) ----
    {
        float bcol = bvec[tid];
        float wx[HID];
        #pragma unroll
        for (int k = 0; k < HID; k++) wx[k] = W[k * NCOL + tid];
        for (int ty = 0; ty < NTY; ty++) {
            float acc = bcol;
            #pragma unroll
            for (int k = 0; k < HID; k++) acc += s_emb[ty * HID + k] * wx[k];
            s_gx[ty * NCOL + tid] = acc;
        }
    }
    // recurrent weights, k-packed — SHARED across all 4 samples
    ull whp[HID / 2];
    #pragma unroll
    for (int q = 0; q < HID / 2; q++)
        whp[q] = pack2(W[(HID + 2 * q) * NCOL + tid],
                       W[(HID + 2 * q + 1) * NCOL + tid]);
    __syncthreads();

    unsigned hb[SPB];
    #pragma unroll
    for (int s = 0; s < SPB; s++) hb[s] = su32(&s_h[s][0]);

    float c = 0.f, cbar = 0.f;          // combine state: warp s (<4) owns sample s

    const size_t O1 = (size_t)NSTEP * NB * HID;
    // obase + s*HID addresses sample s at step t
    size_t obase = (size_t)(blk * SPB) * HID + lane;

    for (int t = 0; t < NSTEP; t++) {
        // ---- 4 independent matvecs, interleaved for ILP (packed fp32x2) ----
        ull a0[SPB], a1[SPB];
        #pragma unroll
        for (int s = 0; s < SPB; s++) { a0[s] = 0; a1[s] = 0; }
        #pragma unroll
        for (int q = 0; q < 8; q++) {
            #pragma unroll
            for (int s = 0; s < SPB; s++) {
                ull hA, hB;
                lds128(hA, hB, hb[s] + q * 16);      // broadcast, conflict-free
                ffma2(a0[s], hA, whp[2 * q]);
                ffma2(a1[s], hB, whp[2 * q + 1]);
            }
        }
        float g[SPB];
        #pragma unroll
        for (int s = 0; s < SPB; s++)
            g[s] = s_gx[(int)s_ty[s][t] * NCOL + tid] + sum2(fadd2(a0[s], a1[s]));

        // ---- activations: warp-uniform branch, 4 samples each ----
        if (warp == 2) {                              // z = tanh
            #pragma unroll
            for (int s = 0; s < SPB; s++) s_act[s][tid] = tanh_fast(g[s]);
        } else if (warp == 6) {                       // delta -> edt (publish exp(-delta*dt))
            #pragma unroll
            for (int s = 0; s < SPB; s++) {
                const float y = BETA * g[s];
                const float del = (fmaxf(y, 0.f) + __logf(1.f + __expf(-fabsf(y)))) * (1.f / BETA);
                out[3 * O1 + obase + s * HID] = del;  // decay_out
                s_act[s][tid] = __expf(-del * s_dt[s][t]);
            }
        } else {                                      // sigmoid gates
            #pragma unroll
            for (int s = 0; s < SPB; s++) {
                const float a = sigmoid_fast(g[s]);
                s_act[s][tid] = a;
                if (warp == 3) out[4 * O1 + obase + s * HID] = a;   // gate_out (o_g)
            }
        }
        __syncthreads();                              // BAR1: all acts ready

        // ---- combine: warp s (<4) handles sample s ----
        if (warp < 4) {
            const float* A = s_act[warp];
            const float ig  = A[lane];
            const float fg  = A[HID + lane];
            const float zg  = A[2 * HID + lane];
            const float og  = A[3 * HID + lane];
            const float ibg = A[4 * HID + lane];
            const float fbg = A[5 * HID + lane];
            const float edt = A[6 * HID + lane];

            const float cn  = fmaf(fg, c, ig * zg);
            const float cbn = fmaf(fbg, cbar, ibg * zg);
            const float ct  = fmaf(cn - cbn, edt, cbn);
            const float hn  = og * tanh_fast(ct);
            c = ct; cbar = cbn;

            s_h[warp][lane] = hn;
            const size_t ob = obase + warp * HID;
            out[ob]          = hn;                    // h_out
            out[O1 + ob]     = cn;                    // c_out
            out[2 * O1 + ob] = cbn;                   // c_bar_out
        }
        obase += (size_t)NB * HID;
        __syncthreads();                              // BAR2: h visible to all warps
    }
}

extern "C" void kernel_launch(void* const* d_in, const int* in_sizes, int n_in,
                              void* d_out, int out_size)
{
    const int*   types = (const int*)d_in[0];
    const float* dtime = (const float*)d_in[1];
    const float* emb   = (const float*)d_in[2];
    const float* W     = (const float*)d_in[3];
    const float* bvec  = (const float*)d_in[4];
    hawkes_kernel<<<NB / SPB, TPB>>>(types, dtime, emb, W, bvec, (float*)d_out);
}

// round 15
// speedup vs baseline: 1.5158x; 1.5158x over previous
#include <cuda_runtime.h>
#include <cstdint>

#define HID   32
#define NCOL  224      // 7*HID gate columns
#define TPB   224      // one thread per column; warp w == gate w
#define NSTEP 2047     // S-1
#define NB    512
#define SEQ   2048
#define NTY   20
#define BETA  0.1f

typedef unsigned long long ull;

__device__ __forceinline__ unsigned su32(const void* p) {
    return (unsigned)__cvta_generic_to_shared(p);
}
__device__ __forceinline__ void ffma2(ull& d, ull a, ull b) {
    asm("fma.rn.f32x2 %0, %1, %2, %0;" : "+l"(d) : "l"(a), "l"(b));
}
__device__ __forceinline__ ull fadd2(ull a, ull b) {
    ull d; asm("add.rn.f32x2 %0, %1, %2;" : "=l"(d) : "l"(a), "l"(b)); return d;
}
__device__ __forceinline__ ull pack2(float a, float b) {
    ull d; asm("mov.b64 %0, {%1, %2};" : "=l"(d) : "f"(a), "f"(b)); return d;
}
__device__ __forceinline__ float sum2(ull v) {
    float a, b; asm("mov.b64 {%0, %1}, %2;" : "=f"(a), "=f"(b) : "l"(v));
    return a + b;
}
__device__ __forceinline__ void lds128(ull& a, ull& b, unsigned addr) {
    asm volatile("ld.shared.v2.u64 {%0, %1}, [%2];" : "=l"(a), "=l"(b) : "r"(addr));
}
// named-barrier producer/consumer primitives (block has exactly 224 threads)
__device__ __forceinline__ void bar_arrive(int id) {
    asm volatile("bar.arrive %0, 224;" :: "r"(id));
}
__device__ __forceinline__ void bar_sync(int id) {
    asm volatile("bar.sync %0, 224;" :: "r"(id) : "memory");
}

__device__ __forceinline__ float tanh_fast(float x) {
    float e = __expf(-2.f * fabsf(x));          // overflow-safe: e in (0,1]
    float t = __fdividef(1.f - e, 1.f + e);
    return copysignf(t, x);
}
__device__ __forceinline__ float sigmoid_fast(float x) {
    return __fdividef(1.f, 1.f + __expf(-x));
}

__global__ __launch_bounds__(TPB, 4)
void hawkes_kernel(const int* __restrict__ types,
                   const float* __restrict__ dtime,
                   const float* __restrict__ emb,
                   const float* __restrict__ W,
                   const float* __restrict__ bvec,
                   float* __restrict__ out)
{
    __shared__ float s_gx[NTY * NCOL];          // x-side pre-activation (incl. bias)
    __shared__ __align__(16) float s_h[HID];    // hidden state (written only by warp 0)
    __shared__ float s_act[NCOL];               // activations; slot 6 = edt
    __shared__ unsigned char s_ty[NSTEP + 1];
    __shared__ float s_dt[NSTEP + 1];
    __shared__ float s_emb[NTY * HID];

    const int tid = threadIdx.x;
    const int bs  = blockIdx.x;

    // ---- prologue ----
    for (int i = tid; i < NTY * HID; i += TPB) s_emb[i] = emb[i];
    for (int t = tid; t < NSTEP; t += TPB) {
        s_ty[t] = (unsigned char)types[bs * SEQ + t];
        s_dt[t] = dtime[bs * SEQ + t + 1];
    }
    if (tid == 0) { s_ty[NSTEP] = 0; s_dt[NSTEP] = 0.f; }   // prefetch pad
    if (tid < HID) s_h[tid] = 0.f;
    __syncthreads();

    // ---- gx lookup table + packed recurrent weights ----
    {
        float bcol = bvec[tid];
        float wx[HID];
        #pragma unroll
        for (int k = 0; k < HID; k++) wx[k] = W[k * NCOL + tid];
        for (int ty = 0; ty < NTY; ty++) {
            float acc = bcol;
            #pragma unroll
            for (int k = 0; k < HID; k++) acc += s_emb[ty * HID + k] * wx[k];
            s_gx[ty * NCOL + tid] = acc;
        }
    }
    ull whp[HID / 2];
    #pragma unroll
    for (int q = 0; q < HID / 2; q++)
        whp[q] = pack2(W[(HID + 2 * q) * NCOL + tid],
                       W[(HID + 2 * q + 1) * NCOL + tid]);
    __syncthreads();

    const int gate = tid >> 5;     // warp-uniform
    const int lane = tid & 31;
    const unsigned hb = su32(s_h);
    float c = 0.f, cbar = 0.f;     // warp-0 state

    const size_t O1 = (size_t)NSTEP * NB * HID;
    size_t obase = (size_t)bs * HID + lane;

    // initial prefetch (t = 0)
    float gxv = s_gx[(int)s_ty[0] * NCOL + tid];
    float dtv = s_dt[0];

    for (int t = 0; t < NSTEP; t++) {
        // ---- matvec: g = gxv + h . W_h[:,col]  (packed fp32x2) ----
        ull a0 = 0, a1 = 0;
        #pragma unroll
        for (int q = 0; q < 8; q++) {
            ull hA, hB;
            lds128(hA, hB, hb + q * 16);           // broadcast, conflict-free
            ffma2(a0, hA, whp[2 * q]);
            ffma2(a1, hB, whp[2 * q + 1]);
        }
        const float g = gxv + sum2(fadd2(a0, a1));
        const int tn = t + 1;

        if (gate == 0) {
            // ---- consumer warp: i-gate stays in register, combine after BAR0 ----
            const float ig = sigmoid_fast(g);
            bar_sync(0);                            // wait for warps 1-6 acts

            const float fg  = s_act[HID + lane];
            const float zg  = s_act[2 * HID + lane];
            const float og  = s_act[3 * HID + lane];
            const float ibg = s_act[4 * HID + lane];
            const float fbg = s_act[5 * HID + lane];
            const float edt = s_act[6 * HID + lane];

            const float cn  = fmaf(fg, c, ig * zg);
            const float cbn = fmaf(fbg, cbar, ibg * zg);
            const float ct  = fmaf(cn - cbn, edt, cbn);
            const float hn  = og * tanh_fast(ct);
            c = ct; cbar = cbn;

            s_h[lane] = hn;                         // publish h(t+1)
            bar_arrive(1);                          // release warps 1-6; no wait here

            out[obase]          = hn;               // h_out   (off critical cycle)
            out[O1 + obase]     = cn;               // c_out
            out[2 * O1 + obase] = cbn;              // c_bar_out
            gxv = s_gx[(int)s_ty[tn] * NCOL + tid]; // prefetch next gx
            dtv = s_dt[tn];
        } else {
            // ---- producer warps: publish act, arrive, prefetch, then wait for h ----
            float a;
            if (gate == 2) {                        // z = tanh
                a = tanh_fast(g);
            } else if (gate == 6) {                 // delta -> edt
                const float y = BETA * g;
                const float del = (fmaxf(y, 0.f) + __logf(1.f + __expf(-fabsf(y)))) * (1.f / BETA);
                const float e = __expf(-del * dtv);
                s_act[tid] = e;
                bar_arrive(0);
                out[3 * O1 + obase] = del;          // decay_out (post-arrive)
                gxv = s_gx[(int)s_ty[tn] * NCOL + tid];
                dtv = s_dt[tn];
                bar_sync(1);                        // wait for h(t+1)
                obase += (size_t)NB * HID;
                continue;
            } else {                                // i,f,o,ib,fb = sigmoid
                a = sigmoid_fast(g);
            }
            s_act[tid] = a;
            bar_arrive(0);
            if (gate == 3) out[4 * O1 + obase] = a; // gate_out (post-arrive)
            gxv = s_gx[(int)s_ty[tn] * NCOL + tid];
            dtv = s_dt[tn];
            bar_sync(1);                            // wait for h(t+1)
        }
        obase += (size_t)NB * HID;
    }
}

extern "C" void kernel_launch(void* const* d_in, const int* in_sizes, int n_in,
                              void* d_out, int out_size)
{
    const int*   types = (const int*)d_in[0];
    const float* dtime = (const float*)d_in[1];
    const float* emb   = (const float*)d_in[2];
    const float* W     = (const float*)d_in[3];
    const float* bvec  = (const float*)d_in[4];
    hawkes_kernel<<<NB, TPB>>>(types, dtime, emb, W, bvec, (float*)d_out);
}

// round 16
// speedup vs baseline: 1.5874x; 1.0472x over previous
#include <cuda_runtime.h>
#include <cstdint>

#define HID   32
#define NCOL  224      // 7*HID gate columns
#define TPB   224      // one thread per column; warp w == gate w
#define NSTEP 2047     // S-1
#define NB    512
#define SEQ   2048
#define NTY   20
#define BETA  0.1f

typedef unsigned long long ull;

__device__ __forceinline__ unsigned su32(const void* p) {
    return (unsigned)__cvta_generic_to_shared(p);
}
__device__ __forceinline__ void ffma2(ull& d, ull a, ull b) {
    asm("fma.rn.f32x2 %0, %1, %2, %0;" : "+l"(d) : "l"(a), "l"(b));
}
__device__ __forceinline__ ull fadd2(ull a, ull b) {
    ull d; asm("add.rn.f32x2 %0, %1, %2;" : "=l"(d) : "l"(a), "l"(b)); return d;
}
__device__ __forceinline__ ull pack2(float a, float b) {
    ull d; asm("mov.b64 %0, {%1, %2};" : "=l"(d) : "f"(a), "f"(b)); return d;
}
__device__ __forceinline__ float sum2(ull v) {
    float a, b; asm("mov.b64 {%0, %1}, %2;" : "=f"(a), "=f"(b) : "l"(v));
    return a + b;
}
__device__ __forceinline__ void lds128(ull& a, ull& b, unsigned addr) {
    asm volatile("ld.shared.v2.u64 {%0, %1}, [%2];" : "=l"(a), "=l"(b) : "r"(addr));
}
// named-barrier producer/consumer primitives (block has exactly 224 threads)
__device__ __forceinline__ void bar_arrive(int id) {
    asm volatile("bar.arrive %0, 224;" :: "r"(id));
}
__device__ __forceinline__ void bar_sync(int id) {
    asm volatile("bar.sync %0, 224;" :: "r"(id) : "memory");
}

// single-MUFU activations (sm_75+ tanh.approx; lat 16 vs ~40-50 for EX2->RCP chains)
__device__ __forceinline__ float tanh_mufu(float x) {
    float y; asm("tanh.approx.f32 %0, %1;" : "=f"(y) : "f"(x)); return y;
}
__device__ __forceinline__ float sigmoid_mufu(float x) {
    return fmaf(tanh_mufu(0.5f * x), 0.5f, 0.5f);
}

__global__ __launch_bounds__(TPB, 4)
void hawkes_kernel(const int* __restrict__ types,
                   const float* __restrict__ dtime,
                   const float* __restrict__ emb,
                   const float* __restrict__ W,
                   const float* __restrict__ bvec,
                   float* __restrict__ out)
{
    __shared__ float s_gx[NTY * NCOL];          // x-side pre-activation (incl. bias)
    __shared__ __align__(16) float s_h[HID];    // hidden state (written only by warp 0)
    __shared__ float s_act[NCOL];               // activations; slot 6 = edt
    __shared__ unsigned char s_ty[NSTEP + 1];
    __shared__ float s_dt[NSTEP + 1];
    __shared__ float s_emb[NTY * HID];

    const int tid = threadIdx.x;
    const int bs  = blockIdx.x;

    // ---- prologue ----
    for (int i = tid; i < NTY * HID; i += TPB) s_emb[i] = emb[i];
    for (int t = tid; t < NSTEP; t += TPB) {
        s_ty[t] = (unsigned char)types[bs * SEQ + t];
        s_dt[t] = dtime[bs * SEQ + t + 1];
    }
    if (tid == 0) { s_ty[NSTEP] = 0; s_dt[NSTEP] = 0.f; }   // prefetch pad
    if (tid < HID) s_h[tid] = 0.f;
    __syncthreads();

    // ---- gx lookup table + packed recurrent weights ----
    {
        float bcol = bvec[tid];
        float wx[HID];
        #pragma unroll
        for (int k = 0; k < HID; k++) wx[k] = W[k * NCOL + tid];
        for (int ty = 0; ty < NTY; ty++) {
            float acc = bcol;
            #pragma unroll
            for (int k = 0; k < HID; k++) acc += s_emb[ty * HID + k] * wx[k];
            s_gx[ty * NCOL + tid] = acc;
        }
    }
    ull whp[HID / 2];
    #pragma unroll
    for (int q = 0; q < HID / 2; q++)
        whp[q] = pack2(W[(HID + 2 * q) * NCOL + tid],
                       W[(HID + 2 * q + 1) * NCOL + tid]);
    __syncthreads();

    const int gate = tid >> 5;     // warp-uniform
    const int lane = tid & 31;
    const unsigned hb = su32(s_h);
    float c = 0.f, cbar = 0.f;     // warp-0 state

    const size_t O1 = (size_t)NSTEP * NB * HID;
    size_t obase = (size_t)bs * HID + lane;

    // initial prefetch (t = 0)
    float gxv = s_gx[(int)s_ty[0] * NCOL + tid];
    float dtv = s_dt[0];

    for (int t = 0; t < NSTEP; t++) {
        // ---- matvec: g = gxv + h . W_h[:,col]  (packed fp32x2) ----
        ull a0 = 0, a1 = 0;
        #pragma unroll
        for (int q = 0; q < 8; q++) {
            ull hA, hB;
            lds128(hA, hB, hb + q * 16);           // broadcast, conflict-free
            ffma2(a0, hA, whp[2 * q]);
            ffma2(a1, hB, whp[2 * q + 1]);
        }
        const float g = gxv + sum2(fadd2(a0, a1));
        const int tn = t + 1;

        if (gate == 0) {
            // ---- consumer warp: i-gate stays in register, combine after BAR0 ----
            const float ig = sigmoid_mufu(g);
            bar_sync(0);                            // wait for warps 1-6 acts

            const float fg  = s_act[HID + lane];
            const float zg  = s_act[2 * HID + lane];
            const float og  = s_act[3 * HID + lane];
            const float ibg = s_act[4 * HID + lane];
            const float fbg = s_act[5 * HID + lane];
            const float edt = s_act[6 * HID + lane];

            const float cn  = fmaf(fg, c, ig * zg);
            const float cbn = fmaf(fbg, cbar, ibg * zg);
            const float ct  = fmaf(cn - cbn, edt, cbn);
            const float hn  = og * tanh_mufu(ct);
            c = ct; cbar = cbn;

            s_h[lane] = hn;                         // publish h(t+1)
            bar_arrive(1);                          // release warps 1-6; no wait here

            out[obase]          = hn;               // h_out   (off critical cycle)
            out[O1 + obase]     = cn;               // c_out
            out[2 * O1 + obase] = cbn;              // c_bar_out
            gxv = s_gx[(int)s_ty[tn] * NCOL + tid]; // prefetch next gx
            dtv = s_dt[tn];
        } else {
            // ---- producer warps: publish act, arrive, prefetch, then wait for h ----
            float a;
            if (gate == 2) {                        // z = tanh (single MUFU)
                a = tanh_mufu(g);
            } else if (gate == 6) {                 // delta -> edt (precise softplus chain)
                const float y = BETA * g;
                const float del = (fmaxf(y, 0.f) + __logf(1.f + __expf(-fabsf(y)))) * (1.f / BETA);
                const float e = __expf(-del * dtv);
                s_act[tid] = e;
                bar_arrive(0);
                out[3 * O1 + obase] = del;          // decay_out (post-arrive)
                gxv = s_gx[(int)s_ty[tn] * NCOL + tid];
                dtv = s_dt[tn];
                bar_sync(1);                        // wait for h(t+1)
                obase += (size_t)NB * HID;
                continue;
            } else {                                // i,f,o,ib,fb = sigmoid (single MUFU)
                a = sigmoid_mufu(g);
            }
            s_act[tid] = a;
            bar_arrive(0);
            if (gate == 3) out[4 * O1 + obase] = a; // gate_out (post-arrive)
            gxv = s_gx[(int)s_ty[tn] * NCOL + tid];
            dtv = s_dt[tn];
            bar_sync(1);                            // wait for h(t+1)
        }
        obase += (size_t)NB * HID;
    }
}

extern "C" void kernel_launch(void* const* d_in, const int* in_sizes, int n_in,
                              void* d_out, int out_size)
{
    const int*   types = (const int*)d_in[0];
    const float* dtime = (const float*)d_in[1];
    const float* emb   = (const float*)d_in[2];
    const float* W     = (const float*)d_in[3];
    const float* bvec  = (const float*)d_in[4];
    hawkes_kernel<<<NB, TPB>>>(types, dtime, emb, W, bvec, (float*)d_out);
}